// round 12
// baseline (speedup 1.0000x reference)
#include <cuda_runtime.h>
#include <cuda_bf16.h>
#include <cstdint>

#define TT 512
#define BB 128
#define KK 20
#define VV 10002
#define PPY 500

#define WS 260    // w_s row stride (u32), 1040B
#define HS 260    // hs_s row stride (u32)
#define GS 21     // g_s row stride (floats)

// ---- static device scratch ----
__device__ float g_Pc[(size_t)VV * 2048];
__device__ float g_Pp[(size_t)PPY * 2048];
__device__ float g_Pt[(size_t)KK * 2048];
__device__ float g_h2[(size_t)TT * BB * 512];
__device__ float g_em[(size_t)TT * BB * KK];
__device__ float g_res[BB];
__device__ unsigned int g_bar[32 * 32];

__device__ __forceinline__ float tanha(float x) {
    float y; asm("tanh.approx.f32 %0, %1;" : "=f"(y) : "f"(x)); return y;
}
__device__ __forceinline__ float sigm(float x) { return 0.5f * tanha(0.5f * x) + 0.5f; }
__device__ __forceinline__ unsigned long long splat2(float w) {
    unsigned long long r; asm("mov.b64 %0, {%1, %1};" : "=l"(r) : "f"(w)); return r;
}
__device__ __forceinline__ void fma2(unsigned long long& a, unsigned long long m, unsigned long long w) {
    asm("fma.rn.f32x2 %0, %1, %2, %0;" : "+l"(a) : "l"(m), "l"(w));
}
__device__ __forceinline__ void unpk(unsigned long long v, float& x, float& y) {
    asm("mov.b64 {%0, %1}, %2;" : "=f"(x), "=f"(y) : "l"(v));
}
__device__ __forceinline__ uint32_t f2tf(float f) {
    uint32_t u; asm("cvt.rna.tf32.f32 %0, %1;" : "=r"(u) : "f"(f)); return u;
}
__device__ __forceinline__ void mma_tf32(float* c,
    uint32_t a0, uint32_t a1, uint32_t a2, uint32_t a3, uint32_t b0, uint32_t b1)
{
    asm("mma.sync.aligned.m16n8k8.row.col.f32.tf32.tf32.f32 "
        "{%0,%1,%2,%3}, {%4,%5,%6,%7}, {%8,%9}, {%0,%1,%2,%3};"
        : "+f"(c[0]), "+f"(c[1]), "+f"(c[2]), "+f"(c[3])
        : "r"(a0), "r"(a1), "r"(a2), "r"(a3), "r"(b0), "r"(b1));
}
#define BARS(id) asm volatile("bar.sync %0, %1;" :: "r"(id), "r"(128) : "memory")

__global__ void bc_init_kernel() {
    if (threadIdx.x < 32) g_bar[threadIdx.x * 32] = 0u;
}

// ---- shared GEMM tile routine: P[rb..][dir*1024+cb..] = A-tile @ W-tile ----
__device__ __forceinline__ void gemm_tile(
    const float* __restrict__ A, int Ne, int De, int doff,
    const float* __restrict__ W, float* __restrict__ P,
    int rb, int cb, int dir)
{
    __shared__ float As[10][132];
    __shared__ float Bs[10][132];
    int tid = threadIdx.x, tx = tid & 15, ty = tid >> 4;
    unsigned long long acc2[8][4];
#pragma unroll
    for (int i = 0; i < 8; ++i)
#pragma unroll
        for (int j = 0; j < 4; ++j) acc2[i][j] = 0ull;

    for (int k0 = 0; k0 < De; k0 += 10) {
#pragma unroll
        for (int i = 0; i < 5; ++i) {
            int idx = tid + i * 256, kc = idx >> 7, r = idx & 127;
            int rg = rb + r;
            As[kc][r] = (rg < Ne) ? A[(size_t)rg * De + k0 + kc] : 0.f;
        }
#pragma unroll
        for (int i = 0; i < 5; ++i) {
            int idx = tid + i * 256, kc = idx >> 7, c = idx & 127;
            Bs[kc][c] = W[(size_t)(cb + c) * 450 + doff + k0 + kc];
        }
        __syncthreads();
#pragma unroll
        for (int k = 0; k < 10; ++k) {
            float4 a0 = *reinterpret_cast<const float4*>(&As[k][tx * 4]);
            float4 a1 = *reinterpret_cast<const float4*>(&As[k][tx * 4 + 64]);
            ulonglong2 b01 = *reinterpret_cast<const ulonglong2*>(&Bs[k][ty * 4]);
            ulonglong2 b23 = *reinterpret_cast<const ulonglong2*>(&Bs[k][ty * 4 + 64]);
            float av[8] = {a0.x, a0.y, a0.z, a0.w, a1.x, a1.y, a1.z, a1.w};
#pragma unroll
            for (int i = 0; i < 8; ++i) {
                unsigned long long a2 = splat2(av[i]);
                fma2(acc2[i][0], b01.x, a2);
                fma2(acc2[i][1], b01.y, a2);
                fma2(acc2[i][2], b23.x, a2);
                fma2(acc2[i][3], b23.y, a2);
            }
        }
        __syncthreads();
    }
#pragma unroll
    for (int i = 0; i < 8; ++i) {
        int r = (i < 4) ? (tx * 4 + i) : (64 + tx * 4 + (i - 4));
        int rg = rb + r;
        if (rg >= Ne) continue;
        float o[8];
        unpk(acc2[i][0], o[0], o[1]);
        unpk(acc2[i][1], o[2], o[3]);
        unpk(acc2[i][2], o[4], o[5]);
        unpk(acc2[i][3], o[6], o[7]);
        float* dst = P + (size_t)rg * 2048 + (size_t)dir * 1024 + cb;
        *reinterpret_cast<float4*>(&dst[ty * 4]) = make_float4(o[0], o[1], o[2], o[3]);
        *reinterpret_cast<float4*>(&dst[ty * 4 + 64]) = make_float4(o[4], o[5], o[6], o[7]);
    }
}

__global__ void __launch_bounds__(256) gemm_c_kernel(
    const float* __restrict__ A, const float* __restrict__ wf, const float* __restrict__ wb)
{
    int dir = blockIdx.z;
    gemm_tile(A, VV, 300, 0, dir ? wb : wf, g_Pc, blockIdx.x * 128, blockIdx.y * 128, dir);
}

__global__ void __launch_bounds__(256) gemm_pt_kernel(
    const float* __restrict__ Ap, const float* __restrict__ At,
    const float* __restrict__ wf, const float* __restrict__ wb)
{
    int dir = blockIdx.z;
    const float* W = dir ? wb : wf;
    if (blockIdx.x < 4)
        gemm_tile(Ap, PPY, 100, 300, W, g_Pp, blockIdx.x * 128, blockIdx.y * 128, dir);
    else
        gemm_tile(At, KK, 50, 400, W, g_Pt, 0, blockIdx.y * 128, dir);
}

// persistent BiLSTM: 128 CTAs = dir(2) x batch-tile-pair(8) x unit-tile(8).
// Each CTA runs TWO independent 128-thread streams (batch tiles of 8),
// sharing smem weights; per-stream named barriers + spin counters so one
// stream's sync latency hides under the other's compute.
#define SMEM_FLOATS (128 * WS + 16 * HS + 256 * GS)

__global__ void __launch_bounds__(256, 1) lstm_kernel(
    const int* __restrict__ xi, const int* __restrict__ pin, const int* __restrict__ ptag,
    const float* __restrict__ whh_f, const float* __restrict__ whh_b,
    const float* __restrict__ bihf, const float* __restrict__ bhhf,
    const float* __restrict__ bihb, const float* __restrict__ bhhb)
{
    extern __shared__ float sm[];
    uint32_t* w_s    = reinterpret_cast<uint32_t*>(sm);              // [128][WS] tf32
    uint32_t* hs_all = reinterpret_cast<uint32_t*>(sm) + 128 * WS;   // [2][8][HS] tf32
    float*    g_all  = sm + 128 * WS + 16 * HS;                      // [2][128][GS] fp32

    int tid = threadIdx.x, bx = blockIdx.x;
    int dir = bx >> 6, loc = bx & 63, bi2 = loc >> 3, ui = loc & 7;
    int stream = tid >> 7, st = tid & 127;
    int bt = bi2 * 2 + stream;          // batch tile 0..15 (8 batches each)
    int b0 = bt * 8;
    int NB = stream + 1;                // named barrier id
    uint32_t* hs_s = hs_all + stream * 8 * HS;
    float*    g_s  = g_all + stream * 128 * GS;

    const float* whh = dir ? whh_b : whh_f;
    const float* bih = dir ? bihb : bihf;
    const float* bhh = dir ? bhhb : bhhf;

    // weights: smem row r = 4j+g  <->  gate-row G = g*256 + ui*32 + j (tf32)
    for (int i = tid; i < 128 * 256; i += 256) {
        int r = i >> 8, h = i & 255;
        int G = ((r & 3) << 8) + ui * 32 + (r >> 2);
        w_s[r * WS + h] = f2tf(whh[(size_t)G * 256 + h]);
    }
    for (int i = tid; i < 16 * HS; i += 256) hs_all[i] = 0u;

    // per-stream identities
    int lane = st & 31, wp = st >> 5;
    int gID = lane >> 2, ac = lane & 3;
    int r0 = wp * 32;                       // phase-1: 32 gate-rows per warp
    int p2_j = st & 31, p2_q = st >> 5;     // phase-2: cells (p2_q, j), (p2_q+4, j)
    int u_g = ui * 32 + p2_j;
    int rb = st >> 4, rcc = st & 15;        // reload: batch rb, 16-h chunk rcc
    int rl_h0 = rcc * 16;
    bool own_chunk = ((rcc >> 1) == ui);

    float biasr[4];
#pragma unroll
    for (int g = 0; g < 4; ++g) {
        int G = (g << 8) + u_g;
        biasr[g] = bih[G] + bhh[G];
    }
    __syncthreads();

    float cs0 = 0.f, cs1 = 0.f;
    unsigned int* barp = g_bar + (dir * 16 + bt) * 32;
    int bg0 = b0 + p2_q;
    int bg1 = bg0 + 4;

    for (int s = 0; s < TT; ++s) {
        int t = dir ? (TT - 1 - s) : s;

        // ---- prefetch phase-2 inputs (independent of h / barriers) ----
        int xv0 = xi[bg0 * TT + t], pv0 = pin[bg0 * TT + t], tv0 = ptag[bg0 * TT + t];
        int xv1 = xi[bg1 * TT + t], pv1 = pin[bg1 * TT + t], tv1 = ptag[bg1 * TT + t];
        const float* pc0 = g_Pc + (size_t)xv0 * 2048 + dir * 1024 + u_g;
        const float* pp0 = g_Pp + (size_t)pv0 * 2048 + dir * 1024 + u_g;
        const float* pt0 = g_Pt + (size_t)tv0 * 2048 + dir * 1024 + u_g;
        const float* pc1 = g_Pc + (size_t)xv1 * 2048 + dir * 1024 + u_g;
        const float* pp1 = g_Pp + (size_t)pv1 * 2048 + dir * 1024 + u_g;
        const float* pt1 = g_Pt + (size_t)tv1 * 2048 + dir * 1024 + u_g;
        float rc[2][4], rp[2][4], rt4[2][4];
#pragma unroll
        for (int g = 0; g < 4; ++g) {
            rc[0][g] = pc0[g * 256]; rp[0][g] = pp0[g * 256]; rt4[0][g] = pt0[g * 256];
            rc[1][g] = pc1[g * 256]; rp[1][g] = pp1[g * 256]; rt4[1][g] = pt1[g * 256];
        }

        if (s > 0) {
            if (st == 0) {
                unsigned v, target = 8u * (unsigned)s;
                do {
                    asm volatile("ld.acquire.gpu.u32 %0, [%1];" : "=r"(v) : "l"(barp) : "memory");
                    if (v >= target) break;
                    __nanosleep(20);
                } while (true);
            }
            BARS(NB);
            // reload peers' h (vectorized, convert to tf32)
            if (!own_chunk) {
                int tp = dir ? (t + 1) : (t - 1);
                const float* src =
                    g_h2 + ((size_t)(tp * BB + b0 + rb)) * 512 + dir * 256 + rl_h0;
                uint32_t* dst = hs_s + rb * HS + rl_h0;
#pragma unroll
                for (int q = 0; q < 4; ++q) {
                    float4 v = *reinterpret_cast<const float4*>(src + q * 4);
                    uint4 o;
                    o.x = f2tf(v.x); o.y = f2tf(v.y); o.z = f2tf(v.z); o.w = f2tf(v.w);
                    *reinterpret_cast<uint4*>(dst + q * 4) = o;
                }
            }
            BARS(NB);
        }

        // phase 1: tf32 mma — warp wp computes rows r0..r0+31 x 8 batches
        {
            float cA[4] = {0.f, 0.f, 0.f, 0.f};
            float cB[4] = {0.f, 0.f, 0.f, 0.f};
            const uint32_t* wrA0 = w_s + (r0 + gID) * WS;
            const uint32_t* wrA1 = wrA0 + 8 * WS;
            const uint32_t* wrB0 = wrA0 + 16 * WS;
            const uint32_t* wrB1 = wrA0 + 24 * WS;
            const uint32_t* hb = hs_s + gID * HS;
#pragma unroll
            for (int k = 0; k < 256; k += 8) {
                uint32_t b0v = hb[k + ac];
                uint32_t b1v = hb[k + ac + 4];
                mma_tf32(cA, wrA0[k + ac], wrA1[k + ac],
                             wrA0[k + ac + 4], wrA1[k + ac + 4], b0v, b1v);
                mma_tf32(cB, wrB0[k + ac], wrB1[k + ac],
                             wrB0[k + ac + 4], wrB1[k + ac + 4], b0v, b1v);
            }
            int bc = 2 * ac;
            g_s[(r0 + gID) * GS + bc]           = cA[0];
            g_s[(r0 + gID) * GS + bc + 1]       = cA[1];
            g_s[(r0 + gID + 8) * GS + bc]       = cA[2];
            g_s[(r0 + gID + 8) * GS + bc + 1]   = cA[3];
            g_s[(r0 + gID + 16) * GS + bc]      = cB[0];
            g_s[(r0 + gID + 16) * GS + bc + 1]  = cB[1];
            g_s[(r0 + gID + 24) * GS + bc]      = cB[2];
            g_s[(r0 + gID + 24) * GS + bc + 1]  = cB[3];
        }
        BARS(NB);

        // phase 2: gates + cell update (2 cells/thread)
#pragma unroll
        for (int cc = 0; cc < 2; ++cc) {
            int bl = p2_q + cc * 4;
            int bg = b0 + bl;
            float g0 = g_s[(p2_j * 4 + 0) * GS + bl];
            float g1 = g_s[(p2_j * 4 + 1) * GS + bl];
            float g2 = g_s[(p2_j * 4 + 2) * GS + bl];
            float g3 = g_s[(p2_j * 4 + 3) * GS + bl];
            float gate0 = biasr[0] + rc[cc][0] + rp[cc][0] + rt4[cc][0] + g0;
            float gate1 = biasr[1] + rc[cc][1] + rp[cc][1] + rt4[cc][1] + g1;
            float gate2 = biasr[2] + rc[cc][2] + rp[cc][2] + rt4[cc][2] + g2;
            float gate3 = biasr[3] + rc[cc][3] + rp[cc][3] + rt4[cc][3] + g3;
            float ig = sigm(gate0);
            float fg = sigm(gate1);
            float gg = tanha(gate2);
            float og = sigm(gate3);
            float c = cc ? cs1 : cs0;
            c = fg * c + ig * gg;
            if (cc) cs1 = c; else cs0 = c;
            float hv = og * tanha(c);
            g_h2[((size_t)(t * BB + bg)) * 512 + dir * 256 + u_g] = hv;
            hs_s[bl * HS + u_g] = f2tf(hv);   // own-slice for next step
        }
        BARS(NB);
        if (st == 0)
            asm volatile("red.release.gpu.global.add.u32 [%0], %1;" :: "l"(barp), "r"(1u) : "memory");
    }
}

// emissions: w_out staged in smem, 64 (t,b) pairs per block
__global__ void __launch_bounds__(256) emis_kernel(
    const float* __restrict__ wout, const float* __restrict__ bout)
{
    __shared__ float ws[KK][520];
    __shared__ float bs[KK];
    int tid = threadIdx.x;
    for (int idx = tid; idx < KK * 512; idx += 256) {
        int k = idx >> 9, c = idx & 511;
        ws[k][c] = wout[idx];
    }
    if (tid < KK) bs[tid] = bout[tid];
    __syncthreads();

    int warp = tid >> 5, lane = tid & 31;
#pragma unroll
    for (int it = 0; it < 8; ++it) {
        int p = blockIdx.x * 64 + it * 8 + warp;   // t*128+b
        const float* hr = g_h2 + (size_t)p * 512;
        float4 h[4];
#pragma unroll
        for (int c = 0; c < 4; ++c)
            h[c] = *reinterpret_cast<const float4*>(&hr[c * 128 + lane * 4]);
        float* em = g_em + (size_t)p * KK;
        for (int k = 0; k < KK; ++k) {
            float s = 0.f;
#pragma unroll
            for (int c = 0; c < 4; ++c) {
                float4 w = *reinterpret_cast<const float4*>(&ws[k][c * 128 + lane * 4]);
                s = fmaf(h[c].x, w.x, s); s = fmaf(h[c].y, w.y, s);
                s = fmaf(h[c].z, w.z, s); s = fmaf(h[c].w, w.w, s);
            }
#pragma unroll
            for (int o = 16; o; o >>= 1) s += __shfl_xor_sync(0xffffffffu, s, o);
            if (lane == 0) em[k] = s + bs[k];
        }
    }
}

// CRF NLL per batch: warp per batch, lane = tag
__global__ void __launch_bounds__(32) crf_kernel(
    const int* __restrict__ y, const float* __restrict__ start,
    const float* __restrict__ endt, const float* __restrict__ trans)
{
    int b = blockIdx.x, lane = threadIdx.x;
    bool act = lane < KK;
    float trc[KK];
#pragma unroll
    for (int j = 0; j < KK; ++j) trc[j] = act ? trans[j * KK + lane] : 0.f;

    float alpha = act ? (start[lane] + g_em[(size_t)b * KK + lane]) : -1e30f;
    for (int t = 1; t < TT; ++t) {
        float e = act ? g_em[((size_t)t * BB + b) * KK + lane] : 0.f;
        float vj[KK], m = -1e30f;
#pragma unroll
        for (int j = 0; j < KK; ++j) {
            float aj = __shfl_sync(0xffffffffu, alpha, j);
            vj[j] = aj + trc[j];
            m = fmaxf(m, vj[j]);
        }
        float ssum = 0.f;
#pragma unroll
        for (int j = 0; j < KK; ++j) ssum += __expf(vj[j] - m);
        alpha = e + m + __logf(ssum);
    }
    float v = act ? (alpha + endt[lane]) : -1e30f;
    float m = v;
#pragma unroll
    for (int o = 16; o; o >>= 1) m = fmaxf(m, __shfl_xor_sync(0xffffffffu, m, o));
    float se = act ? __expf(v - m) : 0.f;
#pragma unroll
    for (int o = 16; o; o >>= 1) se += __shfl_xor_sync(0xffffffffu, se, o);
    float logZ = m + __logf(se);

    const int* yb = y + b * TT;
    float sc = 0.f;
    for (int t = 1 + lane; t < TT; t += 32) {
        int tp = yb[t - 1], tc = yb[t];
        sc += trans[tp * KK + tc] + g_em[((size_t)t * BB + b) * KK + tc];
    }
    if (lane == 0) {
        int t0 = yb[0];
        sc += start[t0] + g_em[(size_t)b * KK + t0] + endt[yb[TT - 1]];
    }
#pragma unroll
    for (int o = 16; o; o >>= 1) sc += __shfl_xor_sync(0xffffffffu, sc, o);
    if (lane == 0) g_res[b] = sc - logZ;
}

__global__ void __launch_bounds__(32) final_kernel(float* __restrict__ out) {
    int lane = threadIdx.x;
    float s = 0.f;
    for (int i = lane; i < BB; i += 32) s += g_res[i];
#pragma unroll
    for (int o = 16; o; o >>= 1) s += __shfl_xor_sync(0xffffffffu, s, o);
    if (lane == 0) out[0] = -s;
}

extern "C" void kernel_launch(void* const* d_in, const int* in_sizes, int n_in,
                              void* d_out, int out_size) {
    const int*   x_idx   = (const int*)d_in[0];
    const int*   y_tags  = (const int*)d_in[1];
    const int*   pretag  = (const int*)d_in[2];
    const int*   pinyin  = (const int*)d_in[3];
    const float* char_emb   = (const float*)d_in[5];
    const float* tag_emb    = (const float*)d_in[6];
    const float* pinyin_emb = (const float*)d_in[7];
    const float* wihf = (const float*)d_in[8];
    const float* whhf = (const float*)d_in[9];
    const float* bihf = (const float*)d_in[10];
    const float* bhhf = (const float*)d_in[11];
    const float* wihb = (const float*)d_in[12];
    const float* whhb = (const float*)d_in[13];
    const float* bihb = (const float*)d_in[14];
    const float* bhhb = (const float*)d_in[15];
    const float* wout  = (const float*)d_in[16];
    const float* bout  = (const float*)d_in[17];
    const float* start = (const float*)d_in[18];
    const float* endt  = (const float*)d_in[19];
    const float* trans = (const float*)d_in[20];
    float* out = (float*)d_out;

    cudaFuncSetAttribute(lstm_kernel,
                         cudaFuncAttributeMaxDynamicSharedMemorySize,
                         SMEM_FLOATS * (int)sizeof(float));

    bc_init_kernel<<<1, 32>>>();
    gemm_c_kernel<<<dim3(79, 8, 2), 256>>>(char_emb, wihf, wihb);
    gemm_pt_kernel<<<dim3(5, 8, 2), 256>>>(pinyin_emb, tag_emb, wihf, wihb);

    lstm_kernel<<<128, 256, SMEM_FLOATS * (int)sizeof(float)>>>(
        x_idx, pinyin, pretag, whhf, whhb, bihf, bhhf, bihb, bhhb);

    emis_kernel<<<(TT * BB) / 64, 256>>>(wout, bout);
    crf_kernel<<<BB, 32>>>(y_tags, start, endt, trans);
    final_kernel<<<1, 32>>>(out);
}

// round 13
// speedup vs baseline: 1.1598x; 1.1598x over previous
#include <cuda_runtime.h>
#include <cuda_bf16.h>
#include <cstdint>

#define TT 512
#define BB 128
#define KK 20
#define VV 10002
#define PPY 500

#define HS 260    // hs_s row stride (u32)
#define GS 21     // g_s row stride (floats)

// ---- static device scratch ----
__device__ float g_Pc[(size_t)VV * 2048];
__device__ float g_Pp[(size_t)PPY * 2048];
__device__ float g_Pt[(size_t)KK * 2048];
__device__ float g_h2[(size_t)TT * BB * 512];
__device__ float g_em[(size_t)TT * BB * KK];
__device__ float g_res[BB];
__device__ uint32_t g_stg[16 * 2 * 16 * 256];   // [group16][parity][batch16][h256] tf32
__device__ unsigned int g_bar[16 * 32];

__device__ __forceinline__ float tanha(float x) {
    float y; asm("tanh.approx.f32 %0, %1;" : "=f"(y) : "f"(x)); return y;
}
__device__ __forceinline__ float sigm(float x) { return 0.5f * tanha(0.5f * x) + 0.5f; }
__device__ __forceinline__ unsigned long long splat2(float w) {
    unsigned long long r; asm("mov.b64 %0, {%1, %1};" : "=l"(r) : "f"(w)); return r;
}
__device__ __forceinline__ void fma2(unsigned long long& a, unsigned long long m, unsigned long long w) {
    asm("fma.rn.f32x2 %0, %1, %2, %0;" : "+l"(a) : "l"(m), "l"(w));
}
__device__ __forceinline__ void unpk(unsigned long long v, float& x, float& y) {
    asm("mov.b64 {%0, %1}, %2;" : "=f"(x), "=f"(y) : "l"(v));
}
__device__ __forceinline__ uint32_t f2tf(float f) {
    uint32_t u; asm("cvt.rna.tf32.f32 %0, %1;" : "=r"(u) : "f"(f)); return u;
}
__device__ __forceinline__ void mma_tf32(float* c,
    uint32_t a0, uint32_t a1, uint32_t a2, uint32_t a3, uint32_t b0, uint32_t b1)
{
    asm("mma.sync.aligned.m16n8k8.row.col.f32.tf32.tf32.f32 "
        "{%0,%1,%2,%3}, {%4,%5,%6,%7}, {%8,%9}, {%0,%1,%2,%3};"
        : "+f"(c[0]), "+f"(c[1]), "+f"(c[2]), "+f"(c[3])
        : "r"(a0), "r"(a1), "r"(a2), "r"(a3), "r"(b0), "r"(b1));
}

__global__ void bc_init_kernel() {
    if (threadIdx.x < 16) g_bar[threadIdx.x * 32] = 0u;
}

// ---- shared GEMM tile routine: P[rb..][dir*1024+cb..] = A-tile @ W-tile ----
__device__ __forceinline__ void gemm_tile(
    const float* __restrict__ A, int Ne, int De, int doff,
    const float* __restrict__ W, float* __restrict__ P,
    int rb, int cb, int dir)
{
    __shared__ float As[10][132];
    __shared__ float Bs[10][132];
    int tid = threadIdx.x, tx = tid & 15, ty = tid >> 4;
    unsigned long long acc2[8][4];
#pragma unroll
    for (int i = 0; i < 8; ++i)
#pragma unroll
        for (int j = 0; j < 4; ++j) acc2[i][j] = 0ull;

    for (int k0 = 0; k0 < De; k0 += 10) {
#pragma unroll
        for (int i = 0; i < 5; ++i) {
            int idx = tid + i * 256, kc = idx >> 7, r = idx & 127;
            int rg = rb + r;
            As[kc][r] = (rg < Ne) ? A[(size_t)rg * De + k0 + kc] : 0.f;
        }
#pragma unroll
        for (int i = 0; i < 5; ++i) {
            int idx = tid + i * 256, kc = idx >> 7, c = idx & 127;
            Bs[kc][c] = W[(size_t)(cb + c) * 450 + doff + k0 + kc];
        }
        __syncthreads();
#pragma unroll
        for (int k = 0; k < 10; ++k) {
            float4 a0 = *reinterpret_cast<const float4*>(&As[k][tx * 4]);
            float4 a1 = *reinterpret_cast<const float4*>(&As[k][tx * 4 + 64]);
            ulonglong2 b01 = *reinterpret_cast<const ulonglong2*>(&Bs[k][ty * 4]);
            ulonglong2 b23 = *reinterpret_cast<const ulonglong2*>(&Bs[k][ty * 4 + 64]);
            float av[8] = {a0.x, a0.y, a0.z, a0.w, a1.x, a1.y, a1.z, a1.w};
#pragma unroll
            for (int i = 0; i < 8; ++i) {
                unsigned long long a2 = splat2(av[i]);
                fma2(acc2[i][0], b01.x, a2);
                fma2(acc2[i][1], b01.y, a2);
                fma2(acc2[i][2], b23.x, a2);
                fma2(acc2[i][3], b23.y, a2);
            }
        }
        __syncthreads();
    }
#pragma unroll
    for (int i = 0; i < 8; ++i) {
        int r = (i < 4) ? (tx * 4 + i) : (64 + tx * 4 + (i - 4));
        int rg = rb + r;
        if (rg >= Ne) continue;
        float o[8];
        unpk(acc2[i][0], o[0], o[1]);
        unpk(acc2[i][1], o[2], o[3]);
        unpk(acc2[i][2], o[4], o[5]);
        unpk(acc2[i][3], o[6], o[7]);
        float* dst = P + (size_t)rg * 2048 + (size_t)dir * 1024 + cb;
        *reinterpret_cast<float4*>(&dst[ty * 4]) = make_float4(o[0], o[1], o[2], o[3]);
        *reinterpret_cast<float4*>(&dst[ty * 4 + 64]) = make_float4(o[4], o[5], o[6], o[7]);
    }
}

__global__ void __launch_bounds__(256) gemm_c_kernel(
    const float* __restrict__ A, const float* __restrict__ wf, const float* __restrict__ wb)
{
    int dir = blockIdx.z;
    gemm_tile(A, VV, 300, 0, dir ? wb : wf, g_Pc, blockIdx.x * 128, blockIdx.y * 128, dir);
}

__global__ void __launch_bounds__(256) gemm_pt_kernel(
    const float* __restrict__ Ap, const float* __restrict__ At,
    const float* __restrict__ wf, const float* __restrict__ wb)
{
    int dir = blockIdx.z;
    const float* W = dir ? wb : wf;
    if (blockIdx.x < 4)
        gemm_tile(Ap, PPY, 100, 300, W, g_Pp, blockIdx.x * 128, blockIdx.y * 128, dir);
    else
        gemm_tile(At, KK, 50, 400, W, g_Pt, 0, blockIdx.y * 128, dir);
}

// persistent BiLSTM: 128 CTAs = dir(2) x batch-tile(8 of 16) x unit-tile(8 of 32).
// Phase-1 A-fragments (weights) register-resident across all 512 steps.
// h exchanged as tf32 via double-buffered staging in L2.
#define SMEM_FLOATS (16 * HS + 128 * GS)

__global__ void __launch_bounds__(256, 1) lstm_kernel(
    const int* __restrict__ xi, const int* __restrict__ pin, const int* __restrict__ ptag,
    const float* __restrict__ whh_f, const float* __restrict__ whh_b,
    const float* __restrict__ bihf, const float* __restrict__ bhhf,
    const float* __restrict__ bihb, const float* __restrict__ bhhb)
{
    extern __shared__ float sm[];
    uint32_t* hs_s = reinterpret_cast<uint32_t*>(sm);   // [16][HS] tf32, batch-major
    float*    g_s  = sm + 16 * HS;                      // [128][GS] fp32

    int tid = threadIdx.x, bx = blockIdx.x;
    int dir = bx >> 6, loc = bx & 63, bi = loc >> 3, ui = loc & 7;
    const float* whh = dir ? whh_b : whh_f;
    const float* bih = dir ? bihb : bihf;
    const float* bhh = dir ? bhhb : bhhf;

    for (int i = tid; i < 16 * HS; i += 256) hs_s[i] = 0u;

    // phase-1 identity (mma): warp wp, rows ar & ar+8 (smem-row space r = 4j+g)
    int lane = tid & 31, wp = tid >> 5;
    int gID = lane >> 2, ac = lane & 3;
    int ar = wp * 16 + gID;
    // phase-2 identity
    int p2_b = tid >> 5, p2_j = tid & 31;
    int u_g = ui * 32 + p2_j;
    // reload identity: batch rb_b, 16-h chunk rcc
    int rb_b = tid >> 4, rcc = tid & 15;
    int rl_h0 = rcc * 16;
    bool own_chunk = ((rcc >> 1) == ui);

    // register-resident A fragments (weights, tf32): 128 u32 per thread
    uint32_t wA[128];
    {
        int rA = ar, rB = ar + 8;
        int GA = ((rA & 3) << 8) + ui * 32 + (rA >> 2);
        int GB = ((rB & 3) << 8) + ui * 32 + (rB >> 2);
        const float* wrA = whh + (size_t)GA * 256;
        const float* wrB = whh + (size_t)GB * 256;
#pragma unroll
        for (int kk = 0; kk < 32; ++kk) {
            int k = kk * 8;
            wA[4 * kk + 0] = f2tf(wrA[k + ac]);
            wA[4 * kk + 1] = f2tf(wrB[k + ac]);
            wA[4 * kk + 2] = f2tf(wrA[k + ac + 4]);
            wA[4 * kk + 3] = f2tf(wrB[k + ac + 4]);
        }
    }

    float biasr[4];
#pragma unroll
    for (int g = 0; g < 4; ++g) {
        int G = (g << 8) + u_g;
        biasr[g] = bih[G] + bhh[G];
    }
    __syncthreads();

    float cs0 = 0.f, cs1 = 0.f;
    unsigned int* barp = g_bar + (dir * 8 + bi) * 32;
    uint32_t* stg_grp = g_stg + (size_t)(dir * 8 + bi) * 2 * 16 * 256;
    int bg0 = bi * 16 + p2_b;
    int bg1 = bg0 + 8;

    for (int s = 0; s < TT; ++s) {
        int t = dir ? (TT - 1 - s) : s;

        // ---- prefetch phase-2 inputs (independent of h / barrier) ----
        int xv0 = xi[bg0 * TT + t], pv0 = pin[bg0 * TT + t], tv0 = ptag[bg0 * TT + t];
        int xv1 = xi[bg1 * TT + t], pv1 = pin[bg1 * TT + t], tv1 = ptag[bg1 * TT + t];
        const float* pc0 = g_Pc + (size_t)xv0 * 2048 + dir * 1024 + u_g;
        const float* pp0 = g_Pp + (size_t)pv0 * 2048 + dir * 1024 + u_g;
        const float* pt0 = g_Pt + (size_t)tv0 * 2048 + dir * 1024 + u_g;
        const float* pc1 = g_Pc + (size_t)xv1 * 2048 + dir * 1024 + u_g;
        const float* pp1 = g_Pp + (size_t)pv1 * 2048 + dir * 1024 + u_g;
        const float* pt1 = g_Pt + (size_t)tv1 * 2048 + dir * 1024 + u_g;
        float pre[2][4];
#pragma unroll
        for (int g = 0; g < 4; ++g) {
            pre[0][g] = biasr[g] + pc0[g * 256] + pp0[g * 256] + pt0[g * 256];
            pre[1][g] = biasr[g] + pc1[g * 256] + pp1[g * 256] + pt1[g * 256];
        }

        if (s > 0) {
            // all reloading threads spin (acquire), then pull tf32 h from staging
            if (!own_chunk) {
                unsigned v, target = 8u * (unsigned)s;
                do {
                    asm volatile("ld.acquire.gpu.u32 %0, [%1];" : "=r"(v) : "l"(barp) : "memory");
                } while (v < target);
                const uint32_t* src =
                    stg_grp + (size_t)(((s - 1) & 1) * 16 + rb_b) * 256 + rl_h0;
                uint32_t* dst = hs_s + rb_b * HS + rl_h0;
#pragma unroll
                for (int q = 0; q < 4; ++q)
                    *reinterpret_cast<uint4*>(dst + q * 4) =
                        *reinterpret_cast<const uint4*>(src + q * 4);
            }
            __syncthreads();
        }

        // phase 1: tf32 mma, A in registers; warp wp -> rows [16wp,16wp+16) x 16 batches
        {
            float cA[4] = {0.f, 0.f, 0.f, 0.f};
            float cB[4] = {0.f, 0.f, 0.f, 0.f};
            const uint32_t* hb0 = hs_s + gID * HS;
            const uint32_t* hb1 = hs_s + (gID + 8) * HS;
#pragma unroll
            for (int kk = 0; kk < 32; ++kk) {
                int k = kk * 8;
                uint32_t b0 = hb0[k + ac];
                uint32_t b1 = hb0[k + ac + 4];
                uint32_t b2 = hb1[k + ac];
                uint32_t b3 = hb1[k + ac + 4];
                mma_tf32(cA, wA[4 * kk], wA[4 * kk + 1], wA[4 * kk + 2], wA[4 * kk + 3], b0, b1);
                mma_tf32(cB, wA[4 * kk], wA[4 * kk + 1], wA[4 * kk + 2], wA[4 * kk + 3], b2, b3);
            }
            int bc = 2 * ac;
            g_s[ar * GS + bc]           = cA[0];
            g_s[ar * GS + bc + 1]       = cA[1];
            g_s[(ar + 8) * GS + bc]     = cA[2];
            g_s[(ar + 8) * GS + bc + 1] = cA[3];
            g_s[ar * GS + bc + 8]       = cB[0];
            g_s[ar * GS + bc + 9]       = cB[1];
            g_s[(ar + 8) * GS + bc + 8] = cB[2];
            g_s[(ar + 8) * GS + bc + 9] = cB[3];
        }
        __syncthreads();

        // phase 2: gates + cell update (2 cells/thread)
        uint32_t* stg_w = stg_grp + (size_t)(s & 1) * 16 * 256;
#pragma unroll
        for (int cc = 0; cc < 2; ++cc) {
            int bl = p2_b + cc * 8;
            int bg = cc ? bg1 : bg0;
            float g0 = g_s[(p2_j * 4 + 0) * GS + bl];
            float g1 = g_s[(p2_j * 4 + 1) * GS + bl];
            float g2 = g_s[(p2_j * 4 + 2) * GS + bl];
            float g3 = g_s[(p2_j * 4 + 3) * GS + bl];
            float ig = sigm(pre[cc][0] + g0);
            float fg = sigm(pre[cc][1] + g1);
            float gg = tanha(pre[cc][2] + g2);
            float og = sigm(pre[cc][3] + g3);
            float c = cc ? cs1 : cs0;
            c = fg * c + ig * gg;
            if (cc) cs1 = c; else cs0 = c;
            float hv = og * tanha(c);
            uint32_t htf = f2tf(hv);
            g_h2[((size_t)(t * BB + bg)) * 512 + dir * 256 + u_g] = hv;
            stg_w[bl * 256 + u_g] = htf;      // peers pull this (tf32)
            hs_s[bl * HS + u_g] = htf;        // own-slice for next step
        }
        __syncthreads();
        if (tid == 0)
            asm volatile("red.release.gpu.global.add.u32 [%0], %1;" :: "l"(barp), "r"(1u) : "memory");
    }
}

// emissions: w_out staged in smem, 64 (t,b) pairs per block
__global__ void __launch_bounds__(256) emis_kernel(
    const float* __restrict__ wout, const float* __restrict__ bout)
{
    __shared__ float ws[KK][520];
    __shared__ float bs[KK];
    int tid = threadIdx.x;
    for (int idx = tid; idx < KK * 512; idx += 256) {
        int k = idx >> 9, c = idx & 511;
        ws[k][c] = wout[idx];
    }
    if (tid < KK) bs[tid] = bout[tid];
    __syncthreads();

    int warp = tid >> 5, lane = tid & 31;
#pragma unroll
    for (int it = 0; it < 8; ++it) {
        int p = blockIdx.x * 64 + it * 8 + warp;   // t*128+b
        const float* hr = g_h2 + (size_t)p * 512;
        float4 h[4];
#pragma unroll
        for (int c = 0; c < 4; ++c)
            h[c] = *reinterpret_cast<const float4*>(&hr[c * 128 + lane * 4]);
        float* em = g_em + (size_t)p * KK;
        for (int k = 0; k < KK; ++k) {
            float s = 0.f;
#pragma unroll
            for (int c = 0; c < 4; ++c) {
                float4 w = *reinterpret_cast<const float4*>(&ws[k][c * 128 + lane * 4]);
                s = fmaf(h[c].x, w.x, s); s = fmaf(h[c].y, w.y, s);
                s = fmaf(h[c].z, w.z, s); s = fmaf(h[c].w, w.w, s);
            }
#pragma unroll
            for (int o = 16; o; o >>= 1) s += __shfl_xor_sync(0xffffffffu, s, o);
            if (lane == 0) em[k] = s + bs[k];
        }
    }
}

// CRF NLL per batch: warp per batch, lane = tag
__global__ void __launch_bounds__(32) crf_kernel(
    const int* __restrict__ y, const float* __restrict__ start,
    const float* __restrict__ endt, const float* __restrict__ trans)
{
    int b = blockIdx.x, lane = threadIdx.x;
    bool act = lane < KK;
    float trc[KK];
#pragma unroll
    for (int j = 0; j < KK; ++j) trc[j] = act ? trans[j * KK + lane] : 0.f;

    float alpha = act ? (start[lane] + g_em[(size_t)b * KK + lane]) : -1e30f;
    for (int t = 1; t < TT; ++t) {
        float e = act ? g_em[((size_t)t * BB + b) * KK + lane] : 0.f;
        float vj[KK], m = -1e30f;
#pragma unroll
        for (int j = 0; j < KK; ++j) {
            float aj = __shfl_sync(0xffffffffu, alpha, j);
            vj[j] = aj + trc[j];
            m = fmaxf(m, vj[j]);
        }
        float ssum = 0.f;
#pragma unroll
        for (int j = 0; j < KK; ++j) ssum += __expf(vj[j] - m);
        alpha = e + m + __logf(ssum);
    }
    float v = act ? (alpha + endt[lane]) : -1e30f;
    float m = v;
#pragma unroll
    for (int o = 16; o; o >>= 1) m = fmaxf(m, __shfl_xor_sync(0xffffffffu, m, o));
    float se = act ? __expf(v - m) : 0.f;
#pragma unroll
    for (int o = 16; o; o >>= 1) se += __shfl_xor_sync(0xffffffffu, se, o);
    float logZ = m + __logf(se);

    const int* yb = y + b * TT;
    float sc = 0.f;
    for (int t = 1 + lane; t < TT; t += 32) {
        int tp = yb[t - 1], tc = yb[t];
        sc += trans[tp * KK + tc] + g_em[((size_t)t * BB + b) * KK + tc];
    }
    if (lane == 0) {
        int t0 = yb[0];
        sc += start[t0] + g_em[(size_t)b * KK + t0] + endt[yb[TT - 1]];
    }
#pragma unroll
    for (int o = 16; o; o >>= 1) sc += __shfl_xor_sync(0xffffffffu, sc, o);
    if (lane == 0) g_res[b] = sc - logZ;
}

__global__ void __launch_bounds__(32) final_kernel(float* __restrict__ out) {
    int lane = threadIdx.x;
    float s = 0.f;
    for (int i = lane; i < BB; i += 32) s += g_res[i];
#pragma unroll
    for (int o = 16; o; o >>= 1) s += __shfl_xor_sync(0xffffffffu, s, o);
    if (lane == 0) out[0] = -s;
}

extern "C" void kernel_launch(void* const* d_in, const int* in_sizes, int n_in,
                              void* d_out, int out_size) {
    const int*   x_idx   = (const int*)d_in[0];
    const int*   y_tags  = (const int*)d_in[1];
    const int*   pretag  = (const int*)d_in[2];
    const int*   pinyin  = (const int*)d_in[3];
    const float* char_emb   = (const float*)d_in[5];
    const float* tag_emb    = (const float*)d_in[6];
    const float* pinyin_emb = (const float*)d_in[7];
    const float* wihf = (const float*)d_in[8];
    const float* whhf = (const float*)d_in[9];
    const float* bihf = (const float*)d_in[10];
    const float* bhhf = (const float*)d_in[11];
    const float* wihb = (const float*)d_in[12];
    const float* whhb = (const float*)d_in[13];
    const float* bihb = (const float*)d_in[14];
    const float* bhhb = (const float*)d_in[15];
    const float* wout  = (const float*)d_in[16];
    const float* bout  = (const float*)d_in[17];
    const float* start = (const float*)d_in[18];
    const float* endt  = (const float*)d_in[19];
    const float* trans = (const float*)d_in[20];
    float* out = (float*)d_out;

    cudaFuncSetAttribute(lstm_kernel,
                         cudaFuncAttributeMaxDynamicSharedMemorySize,
                         SMEM_FLOATS * (int)sizeof(float));

    bc_init_kernel<<<1, 32>>>();
    gemm_c_kernel<<<dim3(79, 8, 2), 256>>>(char_emb, wihf, wihb);
    gemm_pt_kernel<<<dim3(5, 8, 2), 256>>>(pinyin_emb, tag_emb, wihf, wihb);

    lstm_kernel<<<128, 256, SMEM_FLOATS * (int)sizeof(float)>>>(
        x_idx, pinyin, pretag, whhf, whhb, bihf, bhhf, bihb, bhhb);

    emis_kernel<<<(TT * BB) / 64, 256>>>(wout, bout);
    crf_kernel<<<BB, 32>>>(y_tags, start, endt, trans);
    final_kernel<<<1, 32>>>(out);
}